// round 1
// baseline (speedup 1.0000x reference)
#include <cuda_runtime.h>

#define N_ROWS 16384
#define D      2048
#define ETA    0.01f
#define GRID1  592          // 4 CTAs per SM on 148 SMs
#define THREADS 256

// Scratch: per-CTA partial accumulation of sum_k c_k * x_k  (4.85 MB)
__device__ float g_partial[GRID1][D];

__global__ __launch_bounds__(THREADS, 4)
void pass1_kernel(const float* __restrict__ theta,
                  const float* __restrict__ xs)
{
    __shared__ float s_warp[8];
    __shared__ float s_c;

    const int t = threadIdx.x;
    // Each thread owns columns [4t, 4t+4) and [1024+4t, 1024+4t+4)
    const float4 th0 = *reinterpret_cast<const float4*>(theta + 4 * t);
    const float4 th1 = *reinterpret_cast<const float4*>(theta + 1024 + 4 * t);

    float4 a0, a1, b0, b1;
    float4 acc0 = make_float4(0.f, 0.f, 0.f, 0.f);
    float4 acc1 = make_float4(0.f, 0.f, 0.f, 0.f);

    int r = blockIdx.x;
    {
        const float* row = xs + (size_t)r * D;
        a0 = *reinterpret_cast<const float4*>(row + 4 * t);
        a1 = *reinterpret_cast<const float4*>(row + 1024 + 4 * t);
    }

    while (r < N_ROWS) {
        const int rn = r + GRID1;
        if (rn < N_ROWS) {           // prefetch next row while we reduce this one
            const float* rown = xs + (size_t)rn * D;
            b0 = *reinterpret_cast<const float4*>(rown + 4 * t);
            b1 = *reinterpret_cast<const float4*>(rown + 1024 + 4 * t);
        }

        // partial dot <x_r, theta0>
        float s = a0.x * th0.x + a0.y * th0.y + a0.z * th0.z + a0.w * th0.w
                + a1.x * th1.x + a1.y * th1.y + a1.z * th1.z + a1.w * th1.w;

        // warp reduce
        #pragma unroll
        for (int o = 16; o > 0; o >>= 1)
            s += __shfl_down_sync(0xffffffffu, s, o);
        if ((t & 31) == 0) s_warp[t >> 5] = s;
        __syncthreads();

        if (t == 0) {
            float p = s_warp[0];
            #pragma unroll
            for (int w = 1; w < 8; w++) p += s_warp[w];
            s_c = ETA / (1.0f + __expf(p));
        }
        __syncthreads();
        const float c = s_c;

        acc0.x += c * a0.x;  acc0.y += c * a0.y;
        acc0.z += c * a0.z;  acc0.w += c * a0.w;
        acc1.x += c * a1.x;  acc1.y += c * a1.y;
        acc1.z += c * a1.z;  acc1.w += c * a1.w;

        a0 = b0; a1 = b1;
        r = rn;
    }

    float* part = g_partial[blockIdx.x];
    *reinterpret_cast<float4*>(part + 4 * t)        = acc0;
    *reinterpret_cast<float4*>(part + 1024 + 4 * t) = acc1;
}

// Deterministic reduction of the 592 partials + theta0 -> out
// grid 16 x 256: block b covers columns [b*128, b*128+128); two threads per
// column each sum 296 partials, combined through smem.
__global__ void pass2_kernel(const float* __restrict__ theta,
                             float* __restrict__ out)
{
    __shared__ float s_half[THREADS];
    const int lane = threadIdx.x & 127;
    const int half = threadIdx.x >> 7;           // 0 or 1
    const int col  = blockIdx.x * 128 + lane;

    float s = 0.f;
    const int b0 = half * (GRID1 / 2);
    #pragma unroll 8
    for (int b = b0; b < b0 + GRID1 / 2; b++)
        s += g_partial[b][col];

    s_half[threadIdx.x] = s;
    __syncthreads();
    if (half == 0)
        out[col] = theta[col] + s + s_half[threadIdx.x + 128];
}

extern "C" void kernel_launch(void* const* d_in, const int* in_sizes, int n_in,
                              void* d_out, int out_size)
{
    const float* theta = (const float*)d_in[0];
    const float* xs    = (const float*)d_in[1];
    if (n_in >= 2 && in_sizes[0] > in_sizes[1]) {   // guard against input-order surprise
        theta = (const float*)d_in[1];
        xs    = (const float*)d_in[0];
    }
    float* out = (float*)d_out;

    pass1_kernel<<<GRID1, THREADS>>>(theta, xs);
    pass2_kernel<<<D / 128, THREADS>>>(theta, out);
}

// round 2
// speedup vs baseline: 1.2002x; 1.2002x over previous
#include <cuda_runtime.h>

#define N_ROWS 16384
#define D      2048
#define ETA    0.01f
#define GRID1  592          // 4 CTAs per SM on 148 SMs
#define THREADS 256
#define NGROUP 8            // 592 = 8 * 74, 74 = 2 * 37

// Scratch: per-CTA partial accumulation of sum_k c_k * x_k  (4.85 MB)
__device__ float g_partial[GRID1][D];
// Stage-2 scratch: 8 group partials (64 KB)
__device__ float g_stage[NGROUP][D];

__global__ __launch_bounds__(THREADS, 4)
void pass1_kernel(const float* __restrict__ theta,
                  const float* __restrict__ xs)
{
    __shared__ float s_warp[8];
    __shared__ float s_c;

    const int t = threadIdx.x;
    // Each thread owns columns [4t, 4t+4) and [1024+4t, 1024+4t+4)
    const float4 th0 = *reinterpret_cast<const float4*>(theta + 4 * t);
    const float4 th1 = *reinterpret_cast<const float4*>(theta + 1024 + 4 * t);

    float4 a0, a1, b0, b1;
    float4 acc0 = make_float4(0.f, 0.f, 0.f, 0.f);
    float4 acc1 = make_float4(0.f, 0.f, 0.f, 0.f);

    int r = blockIdx.x;
    {
        const float* row = xs + (size_t)r * D;
        a0 = *reinterpret_cast<const float4*>(row + 4 * t);
        a1 = *reinterpret_cast<const float4*>(row + 1024 + 4 * t);
    }

    while (r < N_ROWS) {
        const int rn = r + GRID1;
        if (rn < N_ROWS) {           // prefetch next row while we reduce this one
            const float* rown = xs + (size_t)rn * D;
            b0 = *reinterpret_cast<const float4*>(rown + 4 * t);
            b1 = *reinterpret_cast<const float4*>(rown + 1024 + 4 * t);
        }

        // partial dot <x_r, theta0>
        float s = a0.x * th0.x + a0.y * th0.y + a0.z * th0.z + a0.w * th0.w
                + a1.x * th1.x + a1.y * th1.y + a1.z * th1.z + a1.w * th1.w;

        // warp reduce
        #pragma unroll
        for (int o = 16; o > 0; o >>= 1)
            s += __shfl_down_sync(0xffffffffu, s, o);
        if ((t & 31) == 0) s_warp[t >> 5] = s;
        __syncthreads();

        if (t == 0) {
            float p = s_warp[0];
            #pragma unroll
            for (int w = 1; w < 8; w++) p += s_warp[w];
            s_c = ETA / (1.0f + __expf(p));
        }
        __syncthreads();
        const float c = s_c;

        acc0.x += c * a0.x;  acc0.y += c * a0.y;
        acc0.z += c * a0.z;  acc0.w += c * a0.w;
        acc1.x += c * a1.x;  acc1.y += c * a1.y;
        acc1.z += c * a1.z;  acc1.w += c * a1.w;

        a0 = b0; a1 = b1;
        r = rn;
    }

    float* part = g_partial[blockIdx.x];
    *reinterpret_cast<float4*>(part + 4 * t)        = acc0;
    *reinterpret_cast<float4*>(part + 1024 + 4 * t) = acc1;
}

// Stage A: reduce 592 partials -> 8 group partials.
// grid (16, 8): block (cx, g) covers columns [cx*128, cx*128+128) and
// partial rows [g*74, g*74+74). 256 threads = 2 per column, 37 rows each.
__global__ __launch_bounds__(THREADS)
void pass2a_kernel()
{
    __shared__ float s_half[THREADS];
    const int lane = threadIdx.x & 127;
    const int half = threadIdx.x >> 7;           // 0 or 1
    const int col  = blockIdx.x * 128 + lane;
    const int g    = blockIdx.y;

    float s = 0.f;
    const int b0 = g * 74 + half * 37;
    #pragma unroll 8
    for (int b = b0; b < b0 + 37; b++)
        s += g_partial[b][col];

    s_half[threadIdx.x] = s;
    __syncthreads();
    if (half == 0)
        g_stage[g][col] = s + s_half[threadIdx.x + 128];
}

// Stage B: fold 8 group partials + theta0 -> out. 2048 threads.
__global__ __launch_bounds__(128)
void pass2b_kernel(const float* __restrict__ theta,
                   float* __restrict__ out)
{
    const int col = blockIdx.x * 128 + threadIdx.x;
    float s = theta[col];
    #pragma unroll
    for (int g = 0; g < NGROUP; g++)
        s += g_stage[g][col];
    out[col] = s;
}

extern "C" void kernel_launch(void* const* d_in, const int* in_sizes, int n_in,
                              void* d_out, int out_size)
{
    const float* theta = (const float*)d_in[0];
    const float* xs    = (const float*)d_in[1];
    if (n_in >= 2 && in_sizes[0] > in_sizes[1]) {   // guard against input-order surprise
        theta = (const float*)d_in[1];
        xs    = (const float*)d_in[0];
    }
    float* out = (float*)d_out;

    pass1_kernel<<<GRID1, THREADS>>>(theta, xs);
    pass2a_kernel<<<dim3(16, NGROUP), THREADS>>>();
    pass2b_kernel<<<D / 128, 128>>>(theta, out);
}